// round 3
// baseline (speedup 1.0000x reference)
#include <cuda_runtime.h>
#include <cuda_fp16.h>
#include <math.h>

#define FH 50
#define FW 50
#define FC 1024
#define POOL 7

// fp16 staged feature map (5 MB). Static device array => no allocation.
__device__ __half g_fmh[FH * FW * FC];

// Convert fp32 features -> fp16 (round-to-nearest). Max is order-preserving,
// so max(convert(x)) == convert(max(x)) exactly.
__global__ void __launch_bounds__(256) convert_kernel(const float* __restrict__ fm) {
    int i = blockIdx.x * blockDim.x + threadIdx.x;  // one float4 -> 4 halves
    float4 v = reinterpret_cast<const float4*>(fm)[i];
    union { __half2 h[2]; uint2 u; } p;
    p.h[0] = __floats2half2_rn(v.x, v.y);
    p.h[1] = __floats2half2_rn(v.z, v.w);
    reinterpret_cast<uint2*>(g_fmh)[i] = p.u;
}

// One block per (roi, row-bin). 128 threads, each owns 8 consecutive halves
// (one uint4 lane) of the 1024-channel vector. All 7 column bins of the
// row-bin are accumulated in registers (statically indexed, unrolled).
__global__ void __launch_bounds__(128) roipool_kernel(
    const float* __restrict__ rois,  // [N,4] (y1,x1,y2,x2) normalized
    float* __restrict__ out)         // [N,7,7,1024] fp32
{
    const int by  = blockIdx.x;      // 0..6 row bin
    const int roi = blockIdx.y;

    // ROI corners: fp32 multiply then truncating int cast (matches jnp int32 cast for >=0)
    const float4 r = reinterpret_cast<const float4*>(rois)[roi];
    const int h0 = (int)(FH * r.x);
    const int w0 = (int)(FW * r.y);
    const int h1 = (int)(FH * r.z);
    const int w1 = (int)(FW * r.w);
    const int rh = h1 - h0;
    const int rw = w1 - w0;
    const int hstep = rh / POOL;
    const int wstep = rw / POOL;

    // Row-bin bounds with the reference's empty-bin fixup.
    int sh = by * hstep;
    int eh = (by < POOL - 1) ? sh + hstep : rh;
    if (sh == eh) { if (eh < rh) eh += 1; else sh -= 1; }
    const int ys = max(h0 + sh, 0);
    const int ye = h0 + eh;          // <= FH

    // All 7 column-bin bounds (absolute).
    int xs[POOL], xe[POOL];
    #pragma unroll
    for (int cb = 0; cb < POOL; ++cb) {
        int sw = cb * wstep;
        int ew = (cb < POOL - 1) ? sw + wstep : rw;
        if (sw == ew) { if (ew < rw) ew += 1; else sw -= 1; }
        xs[cb] = max(w0 + sw, 0);
        xe[cb] = w0 + ew;            // <= FW
    }

    const int t = threadIdx.x;       // uint4 lane (8 halves)
    const __half2 ninf = __float2half2_rn(-INFINITY);
    __half2 acc[POOL][4];
    #pragma unroll
    for (int cb = 0; cb < POOL; ++cb) {
        acc[cb][0] = ninf; acc[cb][1] = ninf; acc[cb][2] = ninf; acc[cb][3] = ninf;
    }

    const uint4* fm4 = reinterpret_cast<const uint4*>(g_fmh);  // FC/8 = 128 uint4 per cell
    for (int y = ys; y < ye; ++y) {
        const uint4* row = fm4 + (size_t)(y * FW) * (FC / 8) + t;
        #pragma unroll
        for (int cb = 0; cb < POOL; ++cb) {
            for (int x = xs[cb]; x < xe[cb]; ++x) {
                union { uint4 u; __half2 h[4]; } v;
                v.u = row[(size_t)x * (FC / 8)];
                acc[cb][0] = __hmax2(acc[cb][0], v.h[0]);
                acc[cb][1] = __hmax2(acc[cb][1], v.h[1]);
                acc[cb][2] = __hmax2(acc[cb][2], v.h[2]);
                acc[cb][3] = __hmax2(acc[cb][3], v.h[3]);
            }
        }
    }

    // fp32 output: per col-bin, 8 floats per thread = two float4 stores.
    #pragma unroll
    for (int cb = 0; cb < POOL; ++cb) {
        const size_t o = (((size_t)roi * POOL + by) * POOL + cb) * FC + (size_t)t * 8;
        float2 f0 = __half22float2(acc[cb][0]);
        float2 f1 = __half22float2(acc[cb][1]);
        float2 f2 = __half22float2(acc[cb][2]);
        float2 f3 = __half22float2(acc[cb][3]);
        float4* op = reinterpret_cast<float4*>(out + o);
        op[0] = make_float4(f0.x, f0.y, f1.x, f1.y);
        op[1] = make_float4(f2.x, f2.y, f3.x, f3.y);
    }
}

extern "C" void kernel_launch(void* const* d_in, const int* in_sizes, int n_in,
                              void* d_out, int out_size) {
    const float* features = (const float*)d_in[0];  // [1,50,50,1024] fp32
    const float* rois     = (const float*)d_in[1];  // [N,4] fp32
    const int nrois = in_sizes[1] / 4;

    // Stage features to fp16 (2.56M floats = 640K float4s)
    const int nvec4 = FH * FW * FC / 4;
    convert_kernel<<<nvec4 / 256, 256>>>(features);

    dim3 grid(POOL, nrois);
    roipool_kernel<<<grid, 128>>>(rois, (float*)d_out);
}

// round 4
// speedup vs baseline: 1.8651x; 1.8651x over previous
#include <cuda_runtime.h>
#include <cuda_fp16.h>
#include <math.h>

#define FH 50
#define FW 50
#define FC 1024
#define POOL 7

// fp16 staged feature map (5 MB). Static device arrays => no allocation.
__device__ __half g_fmh[FH * FW * FC];
// Packed geometry per (roi, row-bin, col-pair): ushort8 {ys,ye,xs0,xe0,xs1,xe1,0,0}
#define MAXROI 512
__device__ ushort g_geom[MAXROI * 28 * 8];

// Convert fp32 features -> fp16 (rn). Max is order-preserving, so
// max(convert(x)) == convert(max(x)) exactly.
__global__ void __launch_bounds__(256) convert_kernel(const float* __restrict__ fm) {
    int i = blockIdx.x * blockDim.x + threadIdx.x;  // one float4 -> 4 halves
    float4 v = reinterpret_cast<const float4*>(fm)[i];
    union { __half2 h[2]; uint2 u; } p;
    p.h[0] = __floats2half2_rn(v.x, v.y);
    p.h[1] = __floats2half2_rn(v.z, v.w);
    reinterpret_cast<uint2*>(g_fmh)[i] = p.u;
}

// One thread per (roi, row-bin, col-pair): computes bin bounds once.
__global__ void __launch_bounds__(256) geom_kernel(const float* __restrict__ rois, int nitems) {
    int id = blockIdx.x * blockDim.x + threadIdx.x;
    if (id >= nitems) return;
    const int roi = id / 28;
    const int rem = id - roi * 28;
    const int by = rem >> 2;
    const int cp = rem & 3;

    const float4 r = reinterpret_cast<const float4*>(rois)[roi];
    const int h0 = (int)(FH * r.x);
    const int w0 = (int)(FW * r.y);
    const int h1 = (int)(FH * r.z);
    const int w1 = (int)(FW * r.w);
    const int rh = h1 - h0, rw = w1 - w0;
    const int hstep = rh / POOL, wstep = rw / POOL;

    int sh = by * hstep;
    int eh = (by < POOL - 1) ? sh + hstep : rh;
    if (sh == eh) { if (eh < rh) eh += 1; else sh -= 1; }

    ushort b[8];
    b[0] = (ushort)max(h0 + sh, 0);
    b[1] = (ushort)(h0 + eh);
    #pragma unroll
    for (int k = 0; k < 2; ++k) {
        const int cb = 2 * cp + k;
        int xs = 0, xe = 0;
        if (cb < POOL) {
            int sw = cb * wstep;
            int ew = (cb < POOL - 1) ? sw + wstep : rw;
            if (sw == ew) { if (ew < rw) ew += 1; else sw -= 1; }
            xs = max(w0 + sw, 0);
            xe = w0 + ew;
        }
        b[2 + 2 * k] = (ushort)xs;
        b[3 + 2 * k] = (ushort)xe;
    }
    b[6] = 0; b[7] = 0;
    reinterpret_cast<uint4*>(g_geom)[id] = *reinterpret_cast<uint4*>(b);
}

// One block per (roi, row-bin, col-pair). 128 threads, each owns 8 halves
// (one uint4 lane) of the 1024-channel vector; accumulates both column bins
// of the pair (they share the y range).
__global__ void __launch_bounds__(128) roipool_kernel(float* __restrict__ out) {
    const int gx  = blockIdx.x;      // 0..27 = (row-bin<<2) | col-pair
    const int roi = blockIdx.y;

    uint4 gp = reinterpret_cast<const uint4*>(g_geom)[roi * 28 + gx];
    const ushort* b = reinterpret_cast<const ushort*>(&gp);
    const int ys = b[0], ye = b[1];
    const int xs0 = b[2], xe0 = b[3];
    const int xs1 = b[4], xe1 = b[5];

    const int t = threadIdx.x;       // uint4 lane (8 halves)
    const __half2 ninf = __float2half2_rn(-INFINITY);
    __half2 a00 = ninf, a01 = ninf, a02 = ninf, a03 = ninf;
    __half2 a10 = ninf, a11 = ninf, a12 = ninf, a13 = ninf;

    const uint4* fm4 = reinterpret_cast<const uint4*>(g_fmh);  // FC/8 = 128 uint4 per cell
    for (int y = ys; y < ye; ++y) {
        const uint4* row = fm4 + (size_t)(y * FW) * (FC / 8) + t;
        #pragma unroll 4
        for (int x = xs0; x < xe0; ++x) {
            union { uint4 u; __half2 h[4]; } v;
            v.u = row[(size_t)x * (FC / 8)];
            a00 = __hmax2(a00, v.h[0]);
            a01 = __hmax2(a01, v.h[1]);
            a02 = __hmax2(a02, v.h[2]);
            a03 = __hmax2(a03, v.h[3]);
        }
        #pragma unroll 4
        for (int x = xs1; x < xe1; ++x) {
            union { uint4 u; __half2 h[4]; } v;
            v.u = row[(size_t)x * (FC / 8)];
            a10 = __hmax2(a10, v.h[0]);
            a11 = __hmax2(a11, v.h[1]);
            a12 = __hmax2(a12, v.h[2]);
            a13 = __hmax2(a13, v.h[3]);
        }
    }

    const int by  = gx >> 2;
    const int cb0 = (gx & 3) * 2;

    {
        const size_t o = (((size_t)roi * POOL + by) * POOL + cb0) * FC + (size_t)t * 8;
        float2 f0 = __half22float2(a00), f1 = __half22float2(a01);
        float2 f2 = __half22float2(a02), f3 = __half22float2(a03);
        float4* op = reinterpret_cast<float4*>(out + o);
        op[0] = make_float4(f0.x, f0.y, f1.x, f1.y);
        op[1] = make_float4(f2.x, f2.y, f3.x, f3.y);
    }
    if (cb0 + 1 < POOL) {
        const size_t o = (((size_t)roi * POOL + by) * POOL + cb0 + 1) * FC + (size_t)t * 8;
        float2 f0 = __half22float2(a10), f1 = __half22float2(a11);
        float2 f2 = __half22float2(a12), f3 = __half22float2(a13);
        float4* op = reinterpret_cast<float4*>(out + o);
        op[0] = make_float4(f0.x, f0.y, f1.x, f1.y);
        op[1] = make_float4(f2.x, f2.y, f3.x, f3.y);
    }
}

extern "C" void kernel_launch(void* const* d_in, const int* in_sizes, int n_in,
                              void* d_out, int out_size) {
    const float* features = (const float*)d_in[0];  // [1,50,50,1024] fp32
    const float* rois     = (const float*)d_in[1];  // [N,4] fp32
    const int nrois = in_sizes[1] / 4;

    const int nvec4 = FH * FW * FC / 4;
    convert_kernel<<<nvec4 / 256, 256>>>(features);

    const int nitems = nrois * 28;
    geom_kernel<<<(nitems + 255) / 256, 256>>>(rois, nitems);

    dim3 grid(28, nrois);
    roipool_kernel<<<grid, 128>>>((float*)d_out);
}

// round 5
// speedup vs baseline: 1.8723x; 1.0039x over previous
#include <cuda_runtime.h>
#include <cuda_fp16.h>
#include <math.h>

#define FH 50
#define FW 50
#define FC 1024
#define POOL 7

// fp16 staged feature map (5 MB) + per-(roi,bin) geometry. Static => no alloc.
__device__ __half g_fmh[FH * FW * FC];
#define MAXROI 512
__device__ ushort g_geom[MAXROI * 49 * 4];   // {ys, ye, xs, xe}

// Fused: fp32->fp16 convert (4 float4 per thread, MLP=4) + bin geometry.
// Max is order-preserving under rn-conversion, so pooling in fp16 then
// widening equals converting the fp32 max: error bounded by one fp16 ulp.
__global__ void __launch_bounds__(256) prep_kernel(
    const float* __restrict__ fm, const float* __restrict__ rois, int nitems)
{
    const int tid = blockIdx.x * 256 + threadIdx.x;

    // ---- convert: 640K float4 total, 4 per thread, coalesced ----
    const int base = blockIdx.x * 1024 + threadIdx.x;
    float4 v[4];
    #pragma unroll
    for (int k = 0; k < 4; ++k)
        v[k] = reinterpret_cast<const float4*>(fm)[base + k * 256];
    #pragma unroll
    for (int k = 0; k < 4; ++k) {
        union { __half2 h[2]; uint2 u; } p;
        p.h[0] = __floats2half2_rn(v[k].x, v[k].y);
        p.h[1] = __floats2half2_rn(v[k].z, v[k].w);
        reinterpret_cast<uint2*>(g_fmh)[base + k * 256] = p.u;
    }

    // ---- geometry: one thread per (roi, bin) ----
    if (tid < nitems) {
        const int roi = tid / 49;
        const int rem = tid - roi * 49;
        const int by = rem / POOL;
        const int bx = rem - by * POOL;

        const float4 r = reinterpret_cast<const float4*>(rois)[roi];
        const int h0 = (int)(FH * r.x);
        const int w0 = (int)(FW * r.y);
        const int h1 = (int)(FH * r.z);
        const int w1 = (int)(FW * r.w);
        const int rh = h1 - h0, rw = w1 - w0;
        const int hstep = rh / POOL, wstep = rw / POOL;

        int sh = by * hstep;
        int eh = (by < POOL - 1) ? sh + hstep : rh;
        if (sh == eh) { if (eh < rh) eh += 1; else sh -= 1; }
        int sw = bx * wstep;
        int ew = (bx < POOL - 1) ? sw + wstep : rw;
        if (sw == ew) { if (ew < rw) ew += 1; else sw -= 1; }

        ushort b[4];
        b[0] = (ushort)max(h0 + sh, 0);
        b[1] = (ushort)(h0 + eh);
        b[2] = (ushort)max(w0 + sw, 0);
        b[3] = (ushort)(w0 + ew);
        reinterpret_cast<uint2*>(g_geom)[tid] = *reinterpret_cast<uint2*>(b);
    }
}

// One block per (roi, bin). 128 threads, each owns one uint4 lane (8 halves)
// of the 1024-channel vector. Two feature rows processed per x-iteration to
// double memory-level parallelism (all cells of a bin share one accumulator).
__global__ void __launch_bounds__(128) roipool_kernel(float* __restrict__ out) {
    const int bin = blockIdx.x;      // 0..48
    const int roi = blockIdx.y;

    uint2 gp = reinterpret_cast<const uint2*>(g_geom)[roi * 49 + bin];
    const ushort* b = reinterpret_cast<const ushort*>(&gp);
    const int ys = b[0], ye = b[1], xs = b[2], xe = b[3];

    const int t = threadIdx.x;       // uint4 lane
    const __half2 ninf = __float2half2_rn(-INFINITY);
    __half2 a0 = ninf, a1 = ninf, a2 = ninf, a3 = ninf;

    const uint4* fm4 = reinterpret_cast<const uint4*>(g_fmh);  // 128 uint4/cell
    const int cstride = FC / 8;          // uint4 per cell
    const int rstride = FW * cstride;    // uint4 per feature row

    int y = ys;
    for (; y + 1 < ye; y += 2) {
        const uint4* r0 = fm4 + (size_t)y * rstride + t;
        const uint4* r1 = r0 + rstride;
        #pragma unroll 2
        for (int x = xs; x < xe; ++x) {
            union { uint4 u; __half2 h[4]; } v0, v1;
            v0.u = r0[(size_t)x * cstride];
            v1.u = r1[(size_t)x * cstride];
            a0 = __hmax2(a0, __hmax2(v0.h[0], v1.h[0]));
            a1 = __hmax2(a1, __hmax2(v0.h[1], v1.h[1]));
            a2 = __hmax2(a2, __hmax2(v0.h[2], v1.h[2]));
            a3 = __hmax2(a3, __hmax2(v0.h[3], v1.h[3]));
        }
    }
    if (y < ye) {
        const uint4* r0 = fm4 + (size_t)y * rstride + t;
        #pragma unroll 2
        for (int x = xs; x < xe; ++x) {
            union { uint4 u; __half2 h[4]; } v0;
            v0.u = r0[(size_t)x * cstride];
            a0 = __hmax2(a0, v0.h[0]);
            a1 = __hmax2(a1, v0.h[1]);
            a2 = __hmax2(a2, v0.h[2]);
            a3 = __hmax2(a3, v0.h[3]);
        }
    }

    const size_t o = ((size_t)roi * 49 + bin) * FC + (size_t)t * 8;
    float2 f0 = __half22float2(a0), f1 = __half22float2(a1);
    float2 f2 = __half22float2(a2), f3 = __half22float2(a3);
    float4* op = reinterpret_cast<float4*>(out + o);
    op[0] = make_float4(f0.x, f0.y, f1.x, f1.y);
    op[1] = make_float4(f2.x, f2.y, f3.x, f3.y);
}

extern "C" void kernel_launch(void* const* d_in, const int* in_sizes, int n_in,
                              void* d_out, int out_size) {
    const float* features = (const float*)d_in[0];  // [1,50,50,1024] fp32
    const float* rois     = (const float*)d_in[1];  // [N,4] fp32
    const int nrois = in_sizes[1] / 4;

    // 640K float4 / 1024 per block = 625 blocks; also computes geometry.
    prep_kernel<<<FH * FW * FC / 4 / 1024, 256>>>(features, rois, nrois * 49);

    dim3 grid(49, nrois);
    roipool_kernel<<<grid, 128>>>((float*)d_out);
}

// round 6
// speedup vs baseline: 2.1251x; 1.1350x over previous
#include <cuda_runtime.h>
#include <cuda_fp16.h>
#include <math.h>

#define FH 50
#define FW 50
#define FC 1024
#define POOL 7
#define MAXROI 512

// fp16 staged feature map (5 MB) + per-(roi,bin) geometry. Static => no alloc.
__device__ __half g_fmh[FH * FW * FC];
__device__ ushort g_geom[MAXROI * 49 * 4];   // {ys, ye, xs, xe}

// fp32->fp16 convert (2500x256, one float4/thread — empirically fastest shape)
// plus fused per-(roi,bin) geometry in the first nitems threads.
// Max is order-preserving under rn-conversion, so pooling in fp16 then
// widening equals converting the fp32 max (error <= 1 fp16 ulp, ~4.9e-4 rel).
__global__ void __launch_bounds__(256) convert_kernel(
    const float* __restrict__ fm, const float* __restrict__ rois, int nitems)
{
    const int i = blockIdx.x * 256 + threadIdx.x;
    float4 v = reinterpret_cast<const float4*>(fm)[i];
    union { __half2 h[2]; uint2 u; } p;
    p.h[0] = __floats2half2_rn(v.x, v.y);
    p.h[1] = __floats2half2_rn(v.z, v.w);
    reinterpret_cast<uint2*>(g_fmh)[i] = p.u;

    if (i < nitems) {
        const int roi = i / 49;
        const int rem = i - roi * 49;
        const int by = rem / POOL;
        const int bx = rem - by * POOL;

        const float4 r = reinterpret_cast<const float4*>(rois)[roi];
        const int h0 = (int)(FH * r.x);
        const int w0 = (int)(FW * r.y);
        const int h1 = (int)(FH * r.z);
        const int w1 = (int)(FW * r.w);
        const int rh = h1 - h0, rw = w1 - w0;
        const int hstep = rh / POOL, wstep = rw / POOL;

        int sh = by * hstep;
        int eh = (by < POOL - 1) ? sh + hstep : rh;
        if (sh == eh) { if (eh < rh) eh += 1; else sh -= 1; }
        int sw = bx * wstep;
        int ew = (bx < POOL - 1) ? sw + wstep : rw;
        if (sw == ew) { if (ew < rw) ew += 1; else sw -= 1; }

        ushort b[4];
        b[0] = (ushort)max(h0 + sh, 0);
        b[1] = (ushort)(h0 + eh);
        b[2] = (ushort)max(w0 + sw, 0);
        b[3] = (ushort)(w0 + ew);
        reinterpret_cast<uint2*>(g_geom)[i] = *reinterpret_cast<uint2*>(b);
    }
}

// Persistent pool kernel: one wave of blocks, each strides over (roi,bin)
// items. Next item's geometry is prefetched before processing the current
// item, hiding the dependent-load prologue. 128 threads = one uint4 lane
// (8 halves) of the 1024-channel vector each.
#define PERSIST_BLOCKS 1924   // 148 SMs x 13 resident blocks

__global__ void __launch_bounds__(128, 13) roipool_kernel(
    float* __restrict__ out, int nitems)
{
    const int t = threadIdx.x;       // uint4 lane
    const uint4* fm4 = reinterpret_cast<const uint4*>(g_fmh);  // 128 uint4/cell
    const int cstride = FC / 8;
    const int rstride = FW * cstride;
    const __half2 ninf = __float2half2_rn(-INFINITY);

    int item = blockIdx.x;
    if (item >= nitems) return;
    uint2 g = reinterpret_cast<const uint2*>(g_geom)[item];

    while (true) {
        const int next = item + PERSIST_BLOCKS;
        // Prefetch next geometry; latency overlaps current item's work.
        uint2 gn = make_uint2(0u, 0u);
        if (next < nitems) gn = reinterpret_cast<const uint2*>(g_geom)[next];

        const ushort* b = reinterpret_cast<const ushort*>(&g);
        const int ys = b[0], ye = b[1], xs = b[2], xe = b[3];

        __half2 a0 = ninf, a1 = ninf, a2 = ninf, a3 = ninf;
        for (int y = ys; y < ye; ++y) {
            const uint4* row = fm4 + (size_t)y * rstride + t;
            #pragma unroll 4
            for (int x = xs; x < xe; ++x) {
                union { uint4 u; __half2 h[4]; } v;
                v.u = row[(size_t)x * cstride];
                a0 = __hmax2(a0, v.h[0]);
                a1 = __hmax2(a1, v.h[1]);
                a2 = __hmax2(a2, v.h[2]);
                a3 = __hmax2(a3, v.h[3]);
            }
        }

        const size_t o = (size_t)item * FC + (size_t)t * 8;
        float2 f0 = __half22float2(a0), f1 = __half22float2(a1);
        float2 f2 = __half22float2(a2), f3 = __half22float2(a3);
        float4* op = reinterpret_cast<float4*>(out + o);
        op[0] = make_float4(f0.x, f0.y, f1.x, f1.y);
        op[1] = make_float4(f2.x, f2.y, f3.x, f3.y);

        if (next >= nitems) break;
        item = next;
        g = gn;
    }
}

extern "C" void kernel_launch(void* const* d_in, const int* in_sizes, int n_in,
                              void* d_out, int out_size) {
    const float* features = (const float*)d_in[0];  // [1,50,50,1024] fp32
    const float* rois     = (const float*)d_in[1];  // [N,4] fp32
    const int nrois = in_sizes[1] / 4;
    const int nitems = nrois * 49;

    convert_kernel<<<FH * FW * FC / 4 / 256, 256>>>(features, rois, nitems);
    roipool_kernel<<<PERSIST_BLOCKS, 128>>>((float*)d_out, nitems);
}